// round 1
// baseline (speedup 1.0000x reference)
#include <cuda_runtime.h>
#include <math.h>

// Problem constants
#define BB 2
#define NN 2048
#define CC 1024
#define HH 16
#define DD 64
#define INNER 1024          // HH*DD
#define QK_SCALE 0.125f     // 64^-0.5

// Scratch (no allocations allowed in kernel_launch)
__device__ float g_qkv[(size_t)BB * NN * 3 * INNER];   // [4096, 3072]
__device__ float g_attn[(size_t)BB * NN * INNER];      // [4096, 1024]

// ---------------------------------------------------------------------------
// GEMM: C[M,N] = A[M,K] @ B[K,N] (+ bias).  128x128x8 tiles, 256 threads,
// 8x8 per-thread micro-tile.  A optionally = g_attn, C optionally = g_qkv.
// ---------------------------------------------------------------------------
__global__ __launch_bounds__(256) void gemm128(
    const float* __restrict__ A, const float* __restrict__ Bm,
    float* __restrict__ Cout, const float* __restrict__ bias,
    int M, int N, int K, int aFromAttn, int cToQkv)
{
    const float* __restrict__ Ap = aFromAttn ? g_attn : A;
    float* __restrict__ Cp = cToQkv ? g_qkv : Cout;

    __shared__ float As[8 * 128];
    __shared__ float Bs[8 * 128];

    const int tid  = threadIdx.x;
    const int m0   = blockIdx.y * 128;
    const int n0   = blockIdx.x * 128;
    const int trow = (tid >> 4) * 8;   // 0..120
    const int tcol = (tid & 15) * 8;   // 0..120

    float acc[8][8];
#pragma unroll
    for (int i = 0; i < 8; i++)
#pragma unroll
        for (int j = 0; j < 8; j++) acc[i][j] = 0.0f;

    for (int kt = 0; kt < K; kt += 8) {
        // Load A tile (128 rows x 8 k) transposed into As[kk][m]
#pragma unroll
        for (int i = 0; i < 4; i++) {
            int e  = tid + i * 256;
            int m  = e >> 3;
            int kk = e & 7;
            As[kk * 128 + m] = Ap[(size_t)(m0 + m) * K + kt + kk];
        }
        // Load B tile (8 k x 128 cols) into Bs[kk][n]  (coalesced)
#pragma unroll
        for (int i = 0; i < 4; i++) {
            int e  = tid + i * 256;
            int kk = e >> 7;
            int n  = e & 127;
            Bs[kk * 128 + n] = Bm[(size_t)(kt + kk) * N + n0 + n];
        }
        __syncthreads();

#pragma unroll
        for (int kk = 0; kk < 8; kk++) {
            float4 a0 = *(const float4*)&As[kk * 128 + trow];
            float4 a1 = *(const float4*)&As[kk * 128 + trow + 4];
            float4 b0 = *(const float4*)&Bs[kk * 128 + tcol];
            float4 b1 = *(const float4*)&Bs[kk * 128 + tcol + 4];
            float a[8] = {a0.x, a0.y, a0.z, a0.w, a1.x, a1.y, a1.z, a1.w};
            float b[8] = {b0.x, b0.y, b0.z, b0.w, b1.x, b1.y, b1.z, b1.w};
#pragma unroll
            for (int i = 0; i < 8; i++)
#pragma unroll
                for (int j = 0; j < 8; j++)
                    acc[i][j] = fmaf(a[i], b[j], acc[i][j]);
        }
        __syncthreads();
    }

    // Epilogue: vectorized stores, optional bias
#pragma unroll
    for (int i = 0; i < 8; i++) {
        int row = m0 + trow + i;
        float out[8];
#pragma unroll
        for (int j = 0; j < 8; j++) out[j] = acc[i][j];
        if (bias) {
#pragma unroll
            for (int j = 0; j < 8; j++) out[j] += bias[n0 + tcol + j];
        }
        float4* dst = (float4*)&Cp[(size_t)row * N + n0 + tcol];
        dst[0] = make_float4(out[0], out[1], out[2], out[3]);
        dst[1] = make_float4(out[4], out[5], out[6], out[7]);
    }
}

// ---------------------------------------------------------------------------
// Flash attention: one block per (b, h, 64-query tile). 256 threads as 16x16,
// 4x4 micro-tiles. Online softmax, K/V streamed in 64-row tiles from g_qkv.
// Writes O to g_attn in [B, N, H*D] layout.
// ---------------------------------------------------------------------------
#define SPITCH 65   // smem row pitch (bank-conflict padding)

__global__ __launch_bounds__(256) void flash64()
{
    extern __shared__ float sh[];
    float* Qs = sh;                  // 64 x 65
    float* Ks = sh + 64 * SPITCH;    // 64 x 65
    float* Vs = sh + 2 * 64 * SPITCH;
    float* Ss = sh + 3 * 64 * SPITCH;

    const int tid = threadIdx.x;
    const int ty  = tid >> 4;        // 0..15 -> query rows 4*ty..4*ty+3
    const int tx  = tid & 15;        // 0..15 -> cols 4*tx..4*tx+3
    const int bh  = blockIdx.y;
    const int b   = bh >> 4;
    const int h   = bh & 15;
    const int q0  = blockIdx.x * 64;

    // Q tile (scaled)
    const float* qbase = g_qkv + ((size_t)(b * NN + q0)) * (3 * INNER) + h * DD;
    for (int i = tid; i < 64 * 64; i += 256) {
        int r = i >> 6, d = i & 63;
        Qs[r * SPITCH + d] = qbase[(size_t)r * 3072 + d] * QK_SCALE;
    }

    float mrow[4], lrow[4], o[4][4];
#pragma unroll
    for (int i = 0; i < 4; i++) {
        mrow[i] = -INFINITY;
        lrow[i] = 0.0f;
#pragma unroll
        for (int j = 0; j < 4; j++) o[i][j] = 0.0f;
    }

    for (int kt = 0; kt < NN; kt += 64) {
        const float* kbase = g_qkv + ((size_t)(b * NN + kt)) * 3072 + INNER + h * DD;
        const float* vbase = kbase + INNER;

        __syncthreads();   // previous PV done reading Ks/Vs; first iter: Qs written
        for (int i = tid; i < 64 * 64; i += 256) {
            int r = i >> 6, d = i & 63;
            Ks[r * SPITCH + d] = kbase[(size_t)r * 3072 + d];
            Vs[r * SPITCH + d] = vbase[(size_t)r * 3072 + d];
        }
        __syncthreads();

        // S = Q K^T  (4x4 per thread)
        float s[4][4];
#pragma unroll
        for (int i = 0; i < 4; i++)
#pragma unroll
            for (int j = 0; j < 4; j++) s[i][j] = 0.0f;

#pragma unroll 4
        for (int d = 0; d < 64; d++) {
            float a0 = Qs[(4 * ty + 0) * SPITCH + d];
            float a1 = Qs[(4 * ty + 1) * SPITCH + d];
            float a2 = Qs[(4 * ty + 2) * SPITCH + d];
            float a3 = Qs[(4 * ty + 3) * SPITCH + d];
            float c0 = Ks[(4 * tx + 0) * SPITCH + d];
            float c1 = Ks[(4 * tx + 1) * SPITCH + d];
            float c2 = Ks[(4 * tx + 2) * SPITCH + d];
            float c3 = Ks[(4 * tx + 3) * SPITCH + d];
            s[0][0] = fmaf(a0, c0, s[0][0]); s[0][1] = fmaf(a0, c1, s[0][1]);
            s[0][2] = fmaf(a0, c2, s[0][2]); s[0][3] = fmaf(a0, c3, s[0][3]);
            s[1][0] = fmaf(a1, c0, s[1][0]); s[1][1] = fmaf(a1, c1, s[1][1]);
            s[1][2] = fmaf(a1, c2, s[1][2]); s[1][3] = fmaf(a1, c3, s[1][3]);
            s[2][0] = fmaf(a2, c0, s[2][0]); s[2][1] = fmaf(a2, c1, s[2][1]);
            s[2][2] = fmaf(a2, c2, s[2][2]); s[2][3] = fmaf(a2, c3, s[2][3]);
            s[3][0] = fmaf(a3, c0, s[3][0]); s[3][1] = fmaf(a3, c1, s[3][1]);
            s[3][2] = fmaf(a3, c2, s[3][2]); s[3][3] = fmaf(a3, c3, s[3][3]);
        }

        // Online softmax per row (reduce over the 16 tx lanes = xor group <16)
#pragma unroll
        for (int i = 0; i < 4; i++) {
            float rmax = fmaxf(fmaxf(s[i][0], s[i][1]), fmaxf(s[i][2], s[i][3]));
#pragma unroll
            for (int off = 8; off > 0; off >>= 1)
                rmax = fmaxf(rmax, __shfl_xor_sync(0xffffffffu, rmax, off));
            float nm    = fmaxf(mrow[i], rmax);
            float alpha = __expf(mrow[i] - nm);
            float rsum  = 0.0f;
#pragma unroll
            for (int j = 0; j < 4; j++) {
                float p = __expf(s[i][j] - nm);
                s[i][j] = p;
                rsum += p;
            }
#pragma unroll
            for (int off = 8; off > 0; off >>= 1)
                rsum += __shfl_xor_sync(0xffffffffu, rsum, off);
            lrow[i] = lrow[i] * alpha + rsum;
            mrow[i] = nm;
#pragma unroll
            for (int j = 0; j < 4; j++) o[i][j] *= alpha;
#pragma unroll
            for (int j = 0; j < 4; j++)
                Ss[(4 * ty + i) * SPITCH + 4 * tx + j] = s[i][j];
        }
        __syncthreads();

        // O += P @ V  (thread owns O rows 4*ty.., dim cols 4*tx..)
#pragma unroll 4
        for (int c = 0; c < 64; c++) {
            float p0 = Ss[(4 * ty + 0) * SPITCH + c];
            float p1 = Ss[(4 * ty + 1) * SPITCH + c];
            float p2 = Ss[(4 * ty + 2) * SPITCH + c];
            float p3 = Ss[(4 * ty + 3) * SPITCH + c];
            float v0 = Vs[c * SPITCH + 4 * tx + 0];
            float v1 = Vs[c * SPITCH + 4 * tx + 1];
            float v2 = Vs[c * SPITCH + 4 * tx + 2];
            float v3 = Vs[c * SPITCH + 4 * tx + 3];
            o[0][0] = fmaf(p0, v0, o[0][0]); o[0][1] = fmaf(p0, v1, o[0][1]);
            o[0][2] = fmaf(p0, v2, o[0][2]); o[0][3] = fmaf(p0, v3, o[0][3]);
            o[1][0] = fmaf(p1, v0, o[1][0]); o[1][1] = fmaf(p1, v1, o[1][1]);
            o[1][2] = fmaf(p1, v2, o[1][2]); o[1][3] = fmaf(p1, v3, o[1][3]);
            o[2][0] = fmaf(p2, v0, o[2][0]); o[2][1] = fmaf(p2, v1, o[2][1]);
            o[2][2] = fmaf(p2, v2, o[2][2]); o[2][3] = fmaf(p2, v3, o[2][3]);
            o[3][0] = fmaf(p3, v0, o[3][0]); o[3][1] = fmaf(p3, v1, o[3][1]);
            o[3][2] = fmaf(p3, v2, o[3][2]); o[3][3] = fmaf(p3, v3, o[3][3]);
        }
    }

    // Epilogue: normalize and write [B, N, H*D]
    float* obase = g_attn + ((size_t)(b * NN + q0)) * INNER + h * DD;
#pragma unroll
    for (int i = 0; i < 4; i++) {
        float inv = 1.0f / lrow[i];
#pragma unroll
        for (int j = 0; j < 4; j++)
            obase[(size_t)(4 * ty + i) * INNER + 4 * tx + j] = o[i][j] * inv;
    }
}

// ---------------------------------------------------------------------------
extern "C" void kernel_launch(void* const* d_in, const int* in_sizes, int n_in,
                              void* d_out, int out_size)
{
    const float* x      = (const float*)d_in[0];  // [2, 2048, 1024]
    const float* w_qkv  = (const float*)d_in[1];  // [1024, 3072]
    const float* w_proj = (const float*)d_in[2];  // [1024, 1024]
    const float* b_proj = (const float*)d_in[3];  // [1024]
    float* out = (float*)d_out;                   // [2, 2048, 1024]

    const int smem_flash = 4 * 64 * SPITCH * (int)sizeof(float);  // 66,560 B
    cudaFuncSetAttribute(flash64, cudaFuncAttributeMaxDynamicSharedMemorySize,
                         smem_flash);

    // 1) qkv = x @ w_qkv  -> g_qkv      (M=4096, N=3072, K=1024)
    gemm128<<<dim3(24, 32), 256>>>(x, w_qkv, nullptr, nullptr,
                                   4096, 3072, 1024, 0, 1);
    // 2) flash attention  g_qkv -> g_attn
    flash64<<<dim3(32, 32), 256, smem_flash>>>();
    // 3) out = g_attn @ w_proj + b_proj (M=4096, N=1024, K=1024)
    gemm128<<<dim3(8, 32), 256>>>(nullptr, w_proj, out, b_proj,
                                  4096, 1024, 1024, 1, 0);
}